// round 5
// baseline (speedup 1.0000x reference)
#include <cuda_runtime.h>
#include <cstdint>

// Conv2d N=16,C=128,H=W=56,K=128,3x3,pad1 as 9 shifted GEMMs using
// mma.sync.m16n8k8 tf32. CTA = 128k x 112 pos (2 rows x 56 w), 8 warps.
// Fully-async smem pipeline: 3-slot cp.async ring for W, double-buffered
// cp.async (zero-fill) X prefetched 4 stages early; ONE barrier per stage.

typedef uint32_t u32;

#define X_ELEMS (32 * 232)           // 7424 u32 per X buffer (32c x 4rows x 58, linear)
#define W_ELEMS (128 * 36)           // 4608 u32 per W slot ([128k][36 pad])
#define XB(i)   ((i) * X_ELEMS)
#define WB(i)   (2 * X_ELEMS + (i) * W_ELEMS)
#define SMEM_BYTES ((2 * X_ELEMS + 3 * W_ELEMS) * 4)   // 114688 = 112KB

__device__ u32 g_Wt[36 * 4096];      // [cg*9+rs][k][c32], tf32 bits (RNA)

__device__ __forceinline__ u32 f2tf(float f) {
    u32 r; asm("cvt.rna.tf32.f32 %0, %1;" : "=r"(r) : "f"(f)); return r;
}

__global__ void prep_weights(const float* __restrict__ wt) {
    int idx = blockIdx.x * 256 + threadIdx.x;
    if (idx >= 36 * 4096) return;
    int slab = idx >> 12;
    int k = (idx >> 5) & 127;
    int c = idx & 31;
    int cg = slab / 9, rs = slab % 9;
    g_Wt[idx] = f2tf(wt[(size_t)k * 1152 + (size_t)(cg * 32 + c) * 9 + rs]);
}

__global__ __launch_bounds__(256, 2)
void conv_mma(const float* __restrict__ in,
              const float* __restrict__ bias,
              float* __restrict__ out)
{
    extern __shared__ u32 sm[];
    u32 sbase;
    asm("{ .reg .u64 t; cvta.to.shared.u64 t, %1; cvt.u32.u64 %0, t; }"
        : "=r"(sbase) : "l"(sm));

    const int tid = threadIdx.x;
    const int wid = tid >> 5, lid = tid & 31;
    const int lq = lid & 3, g = lid >> 2;
    const int m0 = (wid & 3) * 32;        // warp m offset (k channels)
    const int wn = wid >> 2;              // warp output row (0/1)

    const int img = blockIdx.x / 28;
    const int h0  = (blockIdx.x % 28) * 2;
    const float* in_n = in + (size_t)img * 401408;

    float acc[2][7][4];
    #pragma unroll
    for (int mt = 0; mt < 2; mt++)
        #pragma unroll
        for (int nt = 0; nt < 7; nt++)
            #pragma unroll
            for (int q = 0; q < 4; q++) acc[mt][nt][q] = 0.f;

    // ---- async X loader: predicated zero-fill cp.async, raw fp32 bits ----
    auto loadX = [&](int cg, int xb) {
        const u32 dbase = sbase + XB(xb) * 4;
        for (int idx = tid; idx < X_ELEMS; idx += 256) {
            int wl  = idx % 58;
            int t   = idx / 58;
            int row = t & 3;
            int c   = t >> 2;
            int hin = h0 - 1 + row;
            int win = wl - 1;
            bool v = ((unsigned)hin < 56u) & ((unsigned)win < 56u);
            const float* src = v ? (in_n + (size_t)(cg * 32 + c) * 3136
                                    + hin * 56 + win)
                                 : in_n;           // clamped, size=0 below
            int sz = v ? 4 : 0;
            u32 dst = dbase + idx * 4;             // layout == c*232+row*58+wl
            asm volatile("cp.async.ca.shared.global [%0], [%1], 4, %2;"
                         :: "r"(dst), "l"(src), "r"(sz) : "memory");
        }
    };

    // ---- async W loader: one 16KB slab into ring slot ----
    auto prefW = [&](int s, int slot) {
        const u32* src = g_Wt + (size_t)s * 4096;
        const u32 dstb = sbase + WB(slot) * 4;
        #pragma unroll
        for (int j = 0; j < 4; j++) {
            int chunk = tid + j * 256;             // 0..1023
            int k = chunk >> 3, cq = chunk & 7;
            u32 dst = dstb + k * 144 + cq * 16;
            asm volatile("cp.async.ca.shared.global [%0], [%1], 16;"
                         :: "r"(dst), "l"(src + chunk * 4) : "memory");
        }
        asm volatile("cp.async.commit_group;" ::: "memory");
    };

    // ---- prologue: group0 = X(cg0)+W(0); group1 = W(1) ----
    loadX(0, 0);
    prefW(0, 0);
    prefW(1, 1);

    for (int s = 0; s < 36; s++) {
        if (s < 35) asm volatile("cp.async.wait_group 1;" ::: "memory");
        else        asm volatile("cp.async.wait_group 0;" ::: "memory");
        __syncthreads();   // groups <= s visible to all; stage s-1 consumers done

        if (s + 2 < 36) {
            if (s % 9 == 5) loadX(s / 9 + 1, (s / 9 + 1) & 1);  // rides group s+2
            prefW(s + 2, (s + 2) % 3);
        }

        const int rs = s % 9, cg = s / 9;
        const u32* Wb = sm + WB(s % 3) + (m0 + g) * 36 + lq;
        const u32* Bb = sm + XB(cg & 1) + lq * 232 + (wn + rs / 3) * 58
                        + g + (rs % 3);

        #pragma unroll
        for (int kk = 0; kk < 4; kk++) {
            u32 a[2][4], b[7][2];
            #pragma unroll
            for (int mt = 0; mt < 2; mt++) {
                const u32* p = Wb + mt * 576 + kk * 8;
                a[mt][0] = p[0];   a[mt][1] = p[288];
                a[mt][2] = p[4];   a[mt][3] = p[292];
            }
            #pragma unroll
            for (int nt = 0; nt < 7; nt++) {
                const u32* p = Bb + kk * 1856 + nt * 8;
                b[nt][0] = p[0];   b[nt][1] = p[928];
            }
            #pragma unroll
            for (int mt = 0; mt < 2; mt++)
                #pragma unroll
                for (int nt = 0; nt < 7; nt++)
                    asm volatile(
                        "mma.sync.aligned.m16n8k8.row.col.f32.tf32.tf32.f32 "
                        "{%0,%1,%2,%3}, {%4,%5,%6,%7}, {%8,%9}, {%0,%1,%2,%3};"
                        : "+f"(acc[mt][nt][0]), "+f"(acc[mt][nt][1]),
                          "+f"(acc[mt][nt][2]), "+f"(acc[mt][nt][3])
                        : "r"(a[mt][0]), "r"(a[mt][1]), "r"(a[mt][2]), "r"(a[mt][3]),
                          "r"(b[nt][0]), "r"(b[nt][1]));
        }
        // no trailing barrier: next iter's top barrier protects slot reuse
    }

    // ---- epilogue: direct STG.64 + bias ----
    #pragma unroll
    for (int mt = 0; mt < 2; mt++)
        #pragma unroll
        for (int h = 0; h < 2; h++) {
            const int k = m0 + mt * 16 + h * 8 + g;
            const float bv = __ldg(&bias[k]);
            float* op = out + (size_t)img * 401408 + (size_t)k * 3136
                        + (h0 + wn) * 56 + lq * 2;
            #pragma unroll
            for (int nt = 0; nt < 7; nt++) {
                float2 v;
                v.x = acc[mt][nt][2 * h + 0] + bv;
                v.y = acc[mt][nt][2 * h + 1] + bv;
                *reinterpret_cast<float2*>(op + nt * 8) = v;
            }
        }
}

extern "C" void kernel_launch(void* const* d_in, const int* in_sizes, int n_in,
                              void* d_out, int out_size)
{
    const float* input  = (const float*)d_in[0];
    const float* weight = (const float*)d_in[1];
    const float* bias   = (const float*)d_in[2];
    float* out = (float*)d_out;

    cudaFuncSetAttribute(conv_mma, cudaFuncAttributeMaxDynamicSharedMemorySize,
                         SMEM_BYTES);

    prep_weights<<<(36 * 4096 + 255) / 256, 256>>>(weight);
    conv_mma<<<448, 256, SMEM_BYTES>>>(input, bias, out);
}